// round 14
// baseline (speedup 1.0000x reference)
#include <cuda_runtime.h>
#include <cstdint>
#include <climits>

#define H 32
#define EPSV 1e-5f
#define N_MAX 10016
#define M_MAX 262144
#define NOUT_MAX 4000000
#define FULLMASK 0xffffffffu

// ---------------- scratch (device globals; no runtime allocation) ----------
// NOTE: never passed as kernel arguments from host (GB300 ATS makes the host
// shadow address silently dereferenceable -> reads/writes go to HOST memory).
__device__ float g_degcnt[N_MAX];
__device__ int   g_eptr[N_MAX + 1];
__device__ float g_h[N_MAX * H];
__device__ float g_agg[N_MAX * H];
__device__ float g_agg2[N_MAX * H];
__device__ float g_x[N_MAX * H];
__device__ float g_xe[M_MAX * H];
__device__ float g_mul[M_MAX * H];
__device__ float g_bmm[(size_t)NOUT_MAX * H];
__device__ float g_colsum[H];
__device__ float g_colsq[H];
__device__ float g_mean[H];
__device__ float g_invstd[H];
__device__ float g_gram[H * H];
__device__ float g_gs[H];
__device__ float g_gw[H];
__device__ int   g_tlo[N_MAX + 1];
__device__ int   g_mx[N_MAX];
__device__ int   g_zlo[N_MAX + 1];
__device__ float g_w1t[2048];
__device__ float g_w2t[2048];

__device__ __forceinline__ void red_add_f4(float* addr, float4 v) {
#if __CUDA_ARCH__ >= 900
    atomicAdd(reinterpret_cast<float4*>(addr), v);
#else
    atomicAdd(addr + 0, v.x);
    atomicAdd(addr + 1, v.y);
    atomicAdd(addr + 2, v.z);
    atomicAdd(addr + 3, v.w);
#endif
}

// tf32 mma: D(16x8) += A(16x8) * B(8x8), A row-major, B col-major
#define MMA_TF32(c, a0, a1, a2, a3, b0, b1) \
    asm volatile("mma.sync.aligned.m16n8k8.row.col.f32.tf32.tf32.f32 " \
                 "{%0,%1,%2,%3}, {%4,%5,%6,%7}, {%8,%9}, {%0,%1,%2,%3};" \
                 : "+f"((c)[0]), "+f"((c)[1]), "+f"((c)[2]), "+f"((c)[3]) \
                 : "r"(a0), "r"(a1), "r"(a2), "r"(a3), "r"(b0), "r"(b1))

__device__ __forceinline__ unsigned cvt_tf32(float f) {
    unsigned u;
    asm("cvt.rna.tf32.f32 %0, %1;" : "=r"(u) : "f"(f));
    return u;
}

// ---------------- slot 1: eptr search + all zeroing + weight transpose ----------
__global__ void k_prep(const int* __restrict__ src,
                       const float* __restrict__ w1, const float* __restrict__ w2,
                       int n, int m) {
    int i = blockIdx.x * blockDim.x + threadIdx.x;
    if (i <= n) {
        int lo = 0, hi = m;
        while (lo < hi) {
            int mid = (lo + hi) >> 1;
            if (src[mid] < i) lo = mid + 1; else hi = mid;
        }
        g_eptr[i] = lo;
    }
    if (i < n) g_degcnt[i] = 0.f;
    if (i < H) { g_colsum[i] = 0.f; g_colsq[i] = 0.f; g_gs[i] = 0.f; g_gw[i] = 0.f; }
    if (i < H * H) g_gram[i] = 0.f;
    if (i < 2048) {
        int c = i & 3;
        int j = (i >> 2) & 31;
        int k4 = i >> 7;
        g_w1t[i] = w1[(k4 * 4 + c) * 32 + j];
        g_w2t[i] = w2[(k4 * 4 + c) * 32 + j];
    }
}

// ---------------- slot 2: in-degree ---------------------------------------------
__global__ void k_deg(const int* __restrict__ dst, int m) {
    int e = blockIdx.x * blockDim.x + threadIdx.x;
    if (e < m) atomicAdd(&g_degcnt[dst[e]], 1.f);
}

// ---------------- slot 3: node embed @ W1 ---------------------------------------
__global__ void k_embed_gemm(const float* __restrict__ emb,
                             const int* __restrict__ x_nodes,
                             const float* __restrict__ w, int n) {
    __shared__ float ws[H * H];
    for (int i = threadIdx.x; i < H * H; i += blockDim.x) ws[i] = w[i];
    __syncthreads();
    int lane = threadIdx.x & 31;
    int row = (blockIdx.x * blockDim.x + threadIdx.x) >> 5;
    if (row >= n) return;
    float v = emb[x_nodes[row] * H + lane];
    float acc = 0.f;
#pragma unroll
    for (int k = 0; k < H; k++)
        acc = fmaf(__shfl_sync(FULLMASK, v, k), ws[k * H + lane], acc);
    g_h[row * H + lane] = acc;
}

// ---------------- slot 4: gather aggregation ------------------------------------
__global__ void k_gather(const int* __restrict__ dst, int n, int which) {
    float* agg = which ? g_agg2 : g_agg;
    int lane = threadIdx.x & 31;
    int i = (blockIdx.x * blockDim.x + threadIdx.x) >> 5;
    if (i >= n) return;
    int e0 = g_eptr[i];
    int e1 = g_eptr[i + 1];
    float acc = 0.f;
    for (int e = e0; e < e1; e++) {
        int d = dst[e];
        acc = fmaf(g_h[d * H + lane], rsqrtf(g_degcnt[d] + 1.f), acc);
    }
    agg[i * H + lane] = acc * rsqrtf(g_degcnt[i] + 1.f);
}

// ---------------- y = agg + h/deg + b (in place) + column stats ------------------
__global__ void k_post(const float* __restrict__ bias, int n, int which) {
    float* agg = which ? g_agg2 : g_agg;
    int lane = threadIdx.x & 31;
    int wid = threadIdx.x >> 5;
    int gw = (blockIdx.x * blockDim.x + threadIdx.x) >> 5;
    int nwarps = (gridDim.x * blockDim.x) >> 5;
    float b = bias[lane];
    float sum = 0.f, sq = 0.f;
    for (int row = gw; row < n; row += nwarps) {
        float rdeg = 1.f / (g_degcnt[row] + 1.f);
        float y = agg[row * H + lane] + g_h[row * H + lane] * rdeg + b;
        agg[row * H + lane] = y;
        sum += y;
        sq += y * y;
    }
    __shared__ float s_sum[8][32];
    __shared__ float s_sq[8][32];
    s_sum[wid][lane] = sum;
    s_sq[wid][lane] = sq;
    __syncthreads();
    if (threadIdx.x < 32) {
        float ts = 0.f, tq = 0.f;
#pragma unroll
        for (int w = 0; w < 8; w++) { ts += s_sum[w][threadIdx.x]; tq += s_sq[w][threadIdx.x]; }
        atomicAdd(&g_colsum[threadIdx.x], ts);
        atomicAdd(&g_colsq[threadIdx.x], tq);
    }
}

__global__ void k_statsfin(const float* __restrict__ ms, float inv_n) {
    int c = threadIdx.x;
    if (c < H) {
        float mean = g_colsum[c] * inv_n;
        float m2 = g_colsq[c] * inv_n;
        float msv = ms[c];
        float var = m2 - msv * (2.f - msv) * mean * mean;
        g_mean[c] = mean;
        g_invstd[c] = rsqrtf(var + EPSV);
        g_colsum[c] = 0.f;
        g_colsq[c] = 0.f;
    }
}

// x1 = relu(gnorm(g_agg)); h2 = x1 @ W2 -> g_h
__global__ void k_norm_gemm(const float* __restrict__ gnw, const float* __restrict__ gnb,
                            const float* __restrict__ ms, const float* __restrict__ w2, int n) {
    __shared__ float ws[H * H];
    for (int i = threadIdx.x; i < H * H; i += blockDim.x) ws[i] = w2[i];
    __syncthreads();
    int lane = threadIdx.x & 31;
    int row = (blockIdx.x * blockDim.x + threadIdx.x) >> 5;
    if (row >= n) return;
    float y = g_agg[row * H + lane];
    float xv = gnw[lane] * (y - ms[lane] * g_mean[lane]) * g_invstd[lane] + gnb[lane];
    xv = fmaxf(xv, 0.f);
    float acc = 0.f;
#pragma unroll
    for (int k = 0; k < H; k++)
        acc = fmaf(__shfl_sync(FULLMASK, xv, k), ws[k * H + lane], acc);
    g_h[row * H + lane] = acc;
}

// x = relu(gnorm(g_agg2)) -> g_x
__global__ void k_norm_only(const float* __restrict__ gnw, const float* __restrict__ gnb,
                            const float* __restrict__ ms, int n) {
    int lane = threadIdx.x & 31;
    int row = (blockIdx.x * blockDim.x + threadIdx.x) >> 5;
    if (row >= n) return;
    float y = g_agg2[row * H + lane];
    float xv = gnw[lane] * (y - ms[lane] * g_mean[lane]) * g_invstd[lane] + gnb[lane];
    g_x[row * H + lane] = fmaxf(xv, 0.f);
}

// per-node triple range start: first t with src[tri_a[t]] >= i
__global__ void k_bounds(const int* __restrict__ src, const int* __restrict__ tri_a,
                         int n, int T) {
    int i = blockIdx.x * blockDim.x + threadIdx.x;
    if (i > n) return;
    int lo = 0, hi = T;
    while (lo < hi) {
        int mid = (lo + hi) >> 1;
        int node = src[tri_a[mid]];
        if (node < i) lo = mid + 1; else hi = mid;
    }
    g_tlo[i] = lo;
}

__global__ void k_maxseg(const int* __restrict__ tri_seg, int n) {
    int lane = threadIdx.x & 31;
    int i = (blockIdx.x * blockDim.x + threadIdx.x) >> 5;
    if (i >= n) return;
    int t0 = g_tlo[i], t1 = g_tlo[i + 1];
    int mx = -1;
    for (int t = t0 + lane; t < t1; t += 32) mx = max(mx, tri_seg[t]);
#pragma unroll
    for (int off = 16; off; off >>= 1) mx = max(mx, __shfl_xor_sync(FULLMASK, mx, off));
    if (lane == 0) g_mx[i] = mx;
}

// zlo[i] = 1 + max(mx[0..i-1]); zlo[n] = tail start.
__global__ void __launch_bounds__(1024) k_prefix(int n) {
    __shared__ int part[1024];
    int tid = threadIdx.x;
    int chunk = (n + 1 + 1023) / 1024;
    int lo = tid * chunk;
    int hi = min(lo + chunk, n + 1);
    int pm = -1;
    for (int i = lo; i < hi; i++)
        if (i < n) pm = max(pm, g_mx[i]);
    part[tid] = pm;
    __syncthreads();
    __shared__ int excl[1024];
    int run = -1;
    if (tid == 0) {
        for (int t = 0; t < 1024; t++) { excl[t] = run; run = max(run, part[t]); }
    }
    __syncthreads();
    run = excl[tid];
    for (int i = lo; i < hi; i++) {
        g_zlo[i] = run + 1;
        if (i < n) run = max(run, g_mx[i]);
    }
}

// ---------------- edge MLPs -----------------------------------------------------
__global__ void k_edge_mlp(const int* __restrict__ src, const int* __restrict__ dst,
                           const float* __restrict__ b1, const float* __restrict__ b2, int m) {
    __shared__ float4 sw1[512];
    __shared__ float4 sw2[512];
    {
        const float4* w1f4 = reinterpret_cast<const float4*>(g_w1t);
        const float4* w2f4 = reinterpret_cast<const float4*>(g_w2t);
        for (int i = threadIdx.x; i < 512; i += blockDim.x) { sw1[i] = w1f4[i]; sw2[i] = w2f4[i]; }
    }
    __syncthreads();
    int lane = threadIdx.x & 31;
    int e = (blockIdx.x * blockDim.x + threadIdx.x) >> 5;
    if (e >= m) return;
    int s = src[e], d = dst[e];
    float xs = g_x[s * H + lane];
    float xd = g_x[d * H + lane];
    float a1 = b1[lane], a2 = b2[lane];
#pragma unroll
    for (int k4 = 0; k4 < 8; k4++) {
        float4 w1v = sw1[k4 * 32 + lane];
        float4 w2v = sw2[k4 * 32 + lane];
        float v0 = __shfl_sync(FULLMASK, xs, k4 * 4 + 0);
        float v1 = __shfl_sync(FULLMASK, xs, k4 * 4 + 1);
        float v2 = __shfl_sync(FULLMASK, xs, k4 * 4 + 2);
        float v3 = __shfl_sync(FULLMASK, xs, k4 * 4 + 3);
        a1 = fmaf(v0, w1v.x, a1); a2 = fmaf(v0, w2v.x, a2);
        a1 = fmaf(v1, w1v.y, a1); a2 = fmaf(v1, w2v.y, a2);
        a1 = fmaf(v2, w1v.z, a1); a2 = fmaf(v2, w2v.z, a2);
        a1 = fmaf(v3, w1v.w, a1); a2 = fmaf(v3, w2v.w, a2);
    }
#pragma unroll
    for (int k4 = 8; k4 < 16; k4++) {
        float4 w1v = sw1[k4 * 32 + lane];
        float4 w2v = sw2[k4 * 32 + lane];
        float v0 = __shfl_sync(FULLMASK, xd, (k4 - 8) * 4 + 0);
        float v1 = __shfl_sync(FULLMASK, xd, (k4 - 8) * 4 + 1);
        float v2 = __shfl_sync(FULLMASK, xd, (k4 - 8) * 4 + 2);
        float v3 = __shfl_sync(FULLMASK, xd, (k4 - 8) * 4 + 3);
        a1 = fmaf(v0, w1v.x, a1); a2 = fmaf(v0, w2v.x, a2);
        a1 = fmaf(v1, w1v.y, a1); a2 = fmaf(v1, w2v.y, a2);
        a1 = fmaf(v2, w1v.z, a1); a2 = fmaf(v2, w2v.z, a2);
        a1 = fmaf(v3, w1v.w, a1); a2 = fmaf(v3, w2v.w, a2);
    }
    g_xe[e * H + lane] = fmaxf(a1, 0.f);
    g_mul[e * H + lane] = fmaxf(a2, 0.f);
}

// ---------------- fused zero+scatter (race-free disjoint ranges) ---------------
__global__ void __launch_bounds__(256) k_scatter_fused(
        const int* __restrict__ tri_a, const int* __restrict__ tri_b,
        const int* __restrict__ tri_seg, int n, int n_out) {
    int i = blockIdx.x;
    int tid = threadIdx.x;
    if (i == n) {
        int rlo = g_zlo[n];
        float4 z = make_float4(0.f, 0.f, 0.f, 0.f);
        float4* base = reinterpret_cast<float4*>(g_bmm) + (size_t)rlo * 8;
        long long nz = (long long)(n_out - rlo) * 8;
        for (long long k = tid; k < nz; k += blockDim.x) base[k] = z;
        return;
    }
    int t0 = g_tlo[i], t1 = g_tlo[i + 1];
    if (t0 == t1) return;
    int rlo = g_zlo[i];
    int rhi = g_mx[i];
    float4 z = make_float4(0.f, 0.f, 0.f, 0.f);
    float4* base = reinterpret_cast<float4*>(g_bmm) + (size_t)rlo * 8;
    long long nz = (long long)(rhi + 1 - rlo) * 8;
    for (long long k = tid; k < nz; k += blockDim.x) base[k] = z;
    __syncthreads();
    long long nt = (long long)(t1 - t0) * 8;
    for (long long k = tid; k < nt; k += blockDim.x) {
        int t = t0 + (int)(k >> 3);
        int sub = (int)(k & 7);
        int a = tri_a[t], b = tri_b[t], sg = tri_seg[t];
        const float4 xe4 = *reinterpret_cast<const float4*>(&g_xe[a * H + sub * 4]);
        const float4 mu4 = *reinterpret_cast<const float4*>(&g_mul[b * H + sub * 4]);
        float4 p = make_float4(xe4.x * mu4.x, xe4.y * mu4.y, xe4.z * mu4.z, xe4.w * mu4.w);
        red_add_f4(&g_bmm[(size_t)sg * H + sub * 4], p);
    }
}

// ---------------- Gram via tensor cores (3xTF32, symmetric: 6 of 8 tiles) --------
// Tiles computed: (ti,bj) in {(0,0),(0,1),(0,2),(0,3),(1,2),(1,3)}.
// Mirrored quadrant rows16-31 x cols0-15 is read as G[l][k] in k_gramfin.
__global__ void __launch_bounds__(256) k_gram(const float* __restrict__ is_edge, int n) {
    int lane = threadIdx.x & 31;
    int wid = threadIdx.x >> 5;
    int gwarp = (blockIdx.x * blockDim.x + threadIdx.x) >> 5;
    int nwarps = (gridDim.x * blockDim.x) >> 5;
    int gq = lane >> 2;   // 0..7 (groupID)
    int tq = lane & 3;    // 0..3 (threadID in group)

    const int TI[6] = {0, 0, 0, 0, 1, 1};
    const int BJ[6] = {0, 1, 2, 3, 2, 3};

    float C[6][4];
#pragma unroll
    for (int t6 = 0; t6 < 6; t6++)
#pragma unroll
        for (int k = 0; k < 4; k++) C[t6][k] = 0.f;
    float sp[4] = {0.f, 0.f, 0.f, 0.f};
    float wp[4] = {0.f, 0.f, 0.f, 0.f};

    int nchunks = (n + 7) >> 3;
    for (int c = gwarp; c < nchunks; c += nwarps) {
        int ra = (c << 3) + tq;
        int rb = ra + 4;
        bool va = ra < n, vb = rb < n;
        float ie0 = va ? __ldg(&is_edge[ra]) : 0.f;
        float ie1 = vb ? __ldg(&is_edge[rb]) : 0.f;
        float e0[4], e1[4];
#pragma unroll
        for (int q = 0; q < 4; q++) {
            e0[q] = va ? g_bmm[(size_t)ra * H + gq + 8 * q] : 0.f;
            e1[q] = vb ? g_bmm[(size_t)rb * H + gq + 8 * q] : 0.f;
        }
#pragma unroll
        for (int q = 0; q < 4; q++) {
            sp[q] += e0[q] + e1[q];
            wp[q] = fmaf(ie0, e0[q], fmaf(ie1, e1[q], wp[q]));
        }
        unsigned hi0[4], hi1[4], lo0[4], lo1[4];
#pragma unroll
        for (int q = 0; q < 4; q++) {
            unsigned hv = cvt_tf32(e0[q]);
            hi0[q] = hv;
            lo0[q] = cvt_tf32(e0[q] - __uint_as_float(hv));
            hv = cvt_tf32(e1[q]);
            hi1[q] = hv;
            lo1[q] = cvt_tf32(e1[q] - __uint_as_float(hv));
        }
#pragma unroll
        for (int t6 = 0; t6 < 6; t6++) {
            int ti = TI[t6], bj = BJ[t6];
            MMA_TF32(C[t6], hi0[2 * ti], hi0[2 * ti + 1], hi1[2 * ti], hi1[2 * ti + 1],
                     hi0[bj], hi1[bj]);
            MMA_TF32(C[t6], hi0[2 * ti], hi0[2 * ti + 1], hi1[2 * ti], hi1[2 * ti + 1],
                     lo0[bj], lo1[bj]);
            MMA_TF32(C[t6], lo0[2 * ti], lo0[2 * ti + 1], lo1[2 * ti], lo1[2 * ti + 1],
                     hi0[bj], hi1[bj]);
        }
    }

    // reduce column sums over the 4 t-lanes of each g-group (result in t==0 lane)
#pragma unroll
    for (int q = 0; q < 4; q++) {
        sp[q] += __shfl_down_sync(FULLMASK, sp[q], 2);
        sp[q] += __shfl_down_sync(FULLMASK, sp[q], 1);
        wp[q] += __shfl_down_sync(FULLMASK, wp[q], 2);
        wp[q] += __shfl_down_sync(FULLMASK, wp[q], 1);
    }

    __shared__ float red[8][H * H];
    __shared__ float ss[8][H];
    __shared__ float ww[8][H];
#pragma unroll
    for (int t6 = 0; t6 < 6; t6++) {
        int ti = TI[t6], bj = BJ[t6];
        int r0 = ti * 16 + gq;
        int c0 = bj * 8 + 2 * tq;
        red[wid][r0 * H + c0]           = C[t6][0];
        red[wid][r0 * H + c0 + 1]       = C[t6][1];
        red[wid][(r0 + 8) * H + c0]     = C[t6][2];
        red[wid][(r0 + 8) * H + c0 + 1] = C[t6][3];
    }
    if (tq == 0) {
#pragma unroll
        for (int q = 0; q < 4; q++) { ss[wid][gq + 8 * q] = sp[q]; ww[wid][gq + 8 * q] = wp[q]; }
    }
    __syncthreads();
    for (int e = threadIdx.x; e < H * H; e += blockDim.x) {
        int r = e >> 5, cc = e & 31;
        if (r >= 16 && cc < 16) continue;   // mirrored quadrant: not computed
        float tsum = 0.f;
#pragma unroll
        for (int w8 = 0; w8 < 8; w8++) tsum += red[w8][e];
        atomicAdd(&g_gram[e], tsum);
    }
    if (threadIdx.x < 32) {
        float ts = 0.f, tw = 0.f;
#pragma unroll
        for (int w8 = 0; w8 < 8; w8++) { ts += ss[w8][threadIdx.x]; tw += ww[w8][threadIdx.x]; }
        atomicAdd(&g_gs[threadIdx.x], ts);
        atomicAdd(&g_gw[threadIdx.x], tw);
    }
}

__global__ void k_gramfin(const float* __restrict__ w3, const float* __restrict__ b3,
                          const float* __restrict__ ms, float fn, float fm) {
    int j = threadIdx.x;
    if (j >= H) return;
    float Wc[34];
#pragma unroll 1
    for (int k = 0; k < 33; k++) Wc[k] = w3[k * H + j];
    Wc[33] = b3[j];
    float inv_n = 1.f / fn;
    double q = 0.0;
    for (int k = 0; k < 34; k++) {
        double rowdot = 0.0;
        for (int l = 0; l < 34; l++) {
            float gkl;
            if (k < 32) {
                if (l < 32) gkl = (k >= 16 && l < 16) ? g_gram[l * H + k] : g_gram[k * H + l];
                else if (l == 32) gkl = g_gw[k];
                else gkl = g_gs[k];
            } else if (k == 32) {
                if (l < 32) gkl = g_gw[l];
                else gkl = fm;
            } else {
                if (l < 32) gkl = g_gs[l];
                else if (l == 32) gkl = fm;
                else gkl = fn;
            }
            rowdot += (double)gkl * (double)Wc[l];
        }
        q += (double)Wc[k] * rowdot;
    }
    double msum = 0.0;
    for (int k = 0; k < 32; k++) msum += (double)g_gs[k] * (double)Wc[k];
    msum += (double)fm * (double)Wc[32];
    msum += (double)fn * (double)Wc[33];
    float mean = (float)(msum * (double)inv_n);
    float m2 = (float)(q * (double)inv_n);
    float msv = ms[j];
    float var = m2 - msv * (2.f - msv) * mean * mean;
    g_mean[j] = mean;
    g_invstd[j] = rsqrtf(var + EPSV);
}

// ---------------- final query kernel --------------------------------------------
__device__ __forceinline__ float compute_xo(int row, int lane, const float* ws,
                                            const float* __restrict__ is_edge,
                                            const float* __restrict__ b3,
                                            const float* __restrict__ gn3w,
                                            const float* __restrict__ gn3b,
                                            const float* __restrict__ gn3ms) {
    float v = g_bmm[(size_t)row * H + lane];
    float acc = fmaf(is_edge[row], ws[32 * H + lane], b3[lane]);
#pragma unroll
    for (int k = 0; k < H; k++)
        acc = fmaf(__shfl_sync(FULLMASK, v, k), ws[k * H + lane], acc);
    float xo = gn3w[lane] * (acc - gn3ms[lane] * g_mean[lane]) * g_invstd[lane] + gn3b[lane];
    return fmaxf(xo, 0.f);
}

__global__ void k_final(const int* __restrict__ pred_idx, const int* __restrict__ trans_perm,
                        const float* __restrict__ pred_mask, const int* __restrict__ pos,
                        const float* __restrict__ is_edge,
                        const float* __restrict__ w3, const float* __restrict__ b3,
                        const float* __restrict__ gn3w, const float* __restrict__ gn3b,
                        const float* __restrict__ gn3ms,
                        const float* __restrict__ lw, const float* __restrict__ lb,
                        float* __restrict__ out, int P) {
    __shared__ float ws[33 * H];
    for (int i = threadIdx.x; i < 33 * H; i += blockDim.x) ws[i] = w3[i];
    __syncthreads();
    int lane = threadIdx.x & 31;
    int p = (blockIdx.x * blockDim.x + threadIdx.x) >> 5;
    if (p >= P) return;
    int r = pred_idx[p];
    int rt = trans_perm[r];
    float mask = pred_mask[p];
    float xo_r = compute_xo(r, lane, ws, is_edge, b3, gn3w, gn3b, gn3ms);
    float xo_t = compute_xo(rt, lane, ws, is_edge, b3, gn3w, gn3b, gn3ms);
    int i0 = pos[2 * p], j0 = pos[2 * p + 1];
    float xx = g_x[i0 * H + lane] * g_x[j0 * H + lane];
    float part = xo_r * xo_t * mask * lw[lane] + xx * lw[H + lane];
#pragma unroll
    for (int off = 16; off; off >>= 1) part += __shfl_down_sync(FULLMASK, part, off);
    if (lane == 0) out[p] = part + lb[0];
}

// ---------------- launch ---------------------------------------------------------
extern "C" void kernel_launch(void* const* d_in, const int* in_sizes, int n_in,
                              void* d_out, int out_size) {
    const float* emb     = (const float*)d_in[0];
    const float* gcn1_w  = (const float*)d_in[1];
    const float* gcn1_b  = (const float*)d_in[2];
    const float* gn1_w   = (const float*)d_in[3];
    const float* gn1_b   = (const float*)d_in[4];
    const float* gn1_ms  = (const float*)d_in[5];
    const float* gcn2_w  = (const float*)d_in[6];
    const float* gcn2_b  = (const float*)d_in[7];
    const float* gn2_w   = (const float*)d_in[8];
    const float* gn2_b   = (const float*)d_in[9];
    const float* gn2_ms  = (const float*)d_in[10];
    const float* mlp1_w  = (const float*)d_in[11];
    const float* mlp1_b  = (const float*)d_in[12];
    const float* mlp2_w  = (const float*)d_in[13];
    const float* mlp2_b  = (const float*)d_in[14];
    const float* mlp3_w  = (const float*)d_in[15];
    const float* mlp3_b  = (const float*)d_in[16];
    const float* gn3_w   = (const float*)d_in[17];
    const float* gn3_b   = (const float*)d_in[18];
    const float* gn3_ms  = (const float*)d_in[19];
    const float* lind_w  = (const float*)d_in[20];
    const float* lind_b  = (const float*)d_in[21];
    const float* is_edge = (const float*)d_in[22];
    const float* pred_mask = (const float*)d_in[23];
    const int* x_nodes   = (const int*)d_in[24];
    const int* ei        = (const int*)d_in[25];
    const int* pos       = (const int*)d_in[26];
    const int* tri_a     = (const int*)d_in[27];
    const int* tri_b     = (const int*)d_in[28];
    const int* tri_seg   = (const int*)d_in[29];
    const int* trans_perm= (const int*)d_in[30];
    const int* pred_idx  = (const int*)d_in[31];

    int N     = in_sizes[24];
    int m     = in_sizes[25] / 2;
    int n_out = in_sizes[22];
    int T     = in_sizes[27];
    int P     = in_sizes[23];

    const int* src = ei;
    const int* dst = ei + m;

    int nodeWarpBlocks = (N * H + 255) / 256;
    int edgeWarpBlocks = (int)(((long long)m * H + 255) / 256);
    int queryWarpBlocks = (P * H + 255) / 256;

    // slots 1-4 (slot 4 profiled = k_gather layer 1)
    k_prep<<<(N + 256) / 256, 256>>>(src, mlp1_w, mlp2_w, N, m);      // 1
    k_deg<<<(m + 255) / 256, 256>>>(dst, m);                          // 2
    k_embed_gemm<<<nodeWarpBlocks, 256>>>(emb, x_nodes, gcn1_w, N);   // 3
    k_gather<<<nodeWarpBlocks, 256>>>(dst, N, 0);                     // 4 <- profiled

    k_bounds<<<(N + 256) / 256, 256>>>(src, tri_a, N, T);
    k_maxseg<<<(N * 32 + 255) / 256, 256>>>(tri_seg, N);
    k_prefix<<<1, 1024>>>(N);

    // GCN layer 1: self-loop + bias + stats, then norm+gemm
    k_post<<<120, 256>>>(gcn1_b, N, 0);
    k_statsfin<<<1, 32>>>(gn1_ms, 1.f / (float)N);
    k_norm_gemm<<<nodeWarpBlocks, 256>>>(gn1_w, gn1_b, gn1_ms, gcn2_w, N);

    // GCN layer 2
    k_gather<<<nodeWarpBlocks, 256>>>(dst, N, 1);
    k_post<<<120, 256>>>(gcn2_b, N, 1);
    k_statsfin<<<1, 32>>>(gn2_ms, 1.f / (float)N);
    k_norm_only<<<nodeWarpBlocks, 256>>>(gn2_w, gn2_b, gn2_ms, N);

    // edge MLPs
    k_edge_mlp<<<edgeWarpBlocks, 256>>>(src, dst, mlp1_b, mlp2_b, m);

    // fused zero+scatter (race-free)
    k_scatter_fused<<<N + 1, 256>>>(tri_a, tri_b, tri_seg, N, n_out);

    // mlp3 GraphNorm statistics via tensor-core Gram (3xTF32, symmetric)
    k_gram<<<444, 256>>>(is_edge, n_out);
    k_gramfin<<<1, 32>>>(mlp3_w, mlp3_b, gn3_ms, (float)n_out, (float)m);

    // final query kernel
    k_final<<<queryWarpBlocks, 256>>>(pred_idx, trans_perm, pred_mask, pos, is_edge,
                                      mlp3_w, mlp3_b, gn3_w, gn3_b, gn3_ms,
                                      lind_w, lind_b, (float*)d_out, P);
}

// round 15
// speedup vs baseline: 1.0828x; 1.0828x over previous
#include <cuda_runtime.h>
#include <cstdint>
#include <climits>

#define H 32
#define EPSV 1e-5f
#define N_MAX 10016
#define M_MAX 262144
#define NOUT_MAX 4000000
#define FULLMASK 0xffffffffu

// ---------------- scratch (device globals; no runtime allocation) ----------
// NOTE: never passed as kernel arguments from host (GB300 ATS makes the host
// shadow address silently dereferenceable -> reads/writes go to HOST memory).
__device__ float g_degcnt[N_MAX];
__device__ int   g_eptr[N_MAX + 1];
__device__ float g_h[N_MAX * H];
__device__ float g_agg[N_MAX * H];
__device__ float g_agg2[N_MAX * H];
__device__ float g_x[N_MAX * H];
__device__ float g_xe[M_MAX * H];
__device__ float g_mul[M_MAX * H];
__device__ float g_bmm[(size_t)NOUT_MAX * H];
__device__ float g_colsum[H];
__device__ float g_colsq[H];
__device__ float g_mean[H];
__device__ float g_invstd[H];
__device__ float g_gram[H * H];
__device__ float g_gs[H];
__device__ float g_gw[H];
__device__ int   g_tlo[N_MAX + 1];
__device__ int   g_mx[N_MAX];
__device__ int   g_zlo[N_MAX + 1];
__device__ float g_w1t[2048];
__device__ float g_w2t[2048];

__device__ __forceinline__ void red_add_f4(float* addr, float4 v) {
#if __CUDA_ARCH__ >= 900
    atomicAdd(reinterpret_cast<float4*>(addr), v);
#else
    atomicAdd(addr + 0, v.x);
    atomicAdd(addr + 1, v.y);
    atomicAdd(addr + 2, v.z);
    atomicAdd(addr + 3, v.w);
#endif
}

// tf32 mma: D(16x8) += A(16x8) * B(8x8), A row-major, B col-major
#define MMA_TF32(c, a0, a1, a2, a3, b0, b1) \
    asm volatile("mma.sync.aligned.m16n8k8.row.col.f32.tf32.tf32.f32 " \
                 "{%0,%1,%2,%3}, {%4,%5,%6,%7}, {%8,%9}, {%0,%1,%2,%3};" \
                 : "+f"((c)[0]), "+f"((c)[1]), "+f"((c)[2]), "+f"((c)[3]) \
                 : "r"(a0), "r"(a1), "r"(a2), "r"(a3), "r"(b0), "r"(b1))

__device__ __forceinline__ unsigned cvt_tf32(float f) {
    unsigned u;
    asm("cvt.rna.tf32.f32 %0, %1;" : "=r"(u) : "f"(f));
    return u;
}

// ---------------- slot 1: eptr search + all zeroing ----------------------------
__global__ void k_prep(const int* __restrict__ src, int n, int m) {
    int i = blockIdx.x * blockDim.x + threadIdx.x;
    if (i <= n) {
        int lo = 0, hi = m;
        while (lo < hi) {
            int mid = (lo + hi) >> 1;
            if (src[mid] < i) lo = mid + 1; else hi = mid;
        }
        g_eptr[i] = lo;
    }
    if (i < n) g_degcnt[i] = 0.f;
    if (i < H) { g_colsum[i] = 0.f; g_colsq[i] = 0.f; g_gs[i] = 0.f; g_gw[i] = 0.f; }
    if (i < H * H) g_gram[i] = 0.f;
}

// ---------------- slot 2: in-degree ---------------------------------------------
__global__ void k_deg(const int* __restrict__ dst, int m) {
    int e = blockIdx.x * blockDim.x + threadIdx.x;
    if (e < m) atomicAdd(&g_degcnt[dst[e]], 1.f);
}

// ---------------- slot 3: node embed @ W1 ---------------------------------------
__global__ void k_embed_gemm(const float* __restrict__ emb,
                             const int* __restrict__ x_nodes,
                             const float* __restrict__ w, int n) {
    __shared__ float ws[H * H];
    for (int i = threadIdx.x; i < H * H; i += blockDim.x) ws[i] = w[i];
    __syncthreads();
    int lane = threadIdx.x & 31;
    int row = (blockIdx.x * blockDim.x + threadIdx.x) >> 5;
    if (row >= n) return;
    float v = emb[x_nodes[row] * H + lane];
    float acc = 0.f;
#pragma unroll
    for (int k = 0; k < H; k++)
        acc = fmaf(__shfl_sync(FULLMASK, v, k), ws[k * H + lane], acc);
    g_h[row * H + lane] = acc;
}

// ---------------- slot 4: fused gather aggregation + self-loop + bias + stats ---
// agg[i] = rsqrt(deg_i)*sum_e h[dst_e]*rsqrt(deg_d) + h[i]/deg_i + b; col stats.
__global__ void k_gather_post(const int* __restrict__ dst, const float* __restrict__ bias,
                              int n, int which) {
    float* agg = which ? g_agg2 : g_agg;
    int lane = threadIdx.x & 31;
    int wid = threadIdx.x >> 5;
    int i = (blockIdx.x * blockDim.x + threadIdx.x) >> 5;
    float sum = 0.f, sq = 0.f;
    if (i < n) {
        int e0 = g_eptr[i];
        int e1 = g_eptr[i + 1];
        float acc = 0.f;
        for (int e = e0; e < e1; e++) {
            int d = dst[e];
            acc = fmaf(g_h[d * H + lane], rsqrtf(g_degcnt[d] + 1.f), acc);
        }
        float degp1 = g_degcnt[i] + 1.f;
        float y = acc * rsqrtf(degp1) + g_h[i * H + lane] * (1.f / degp1) + bias[lane];
        agg[i * H + lane] = y;
        sum = y;
        sq = y * y;
    }
    __shared__ float s_sum[8][32];
    __shared__ float s_sq[8][32];
    s_sum[wid][lane] = sum;
    s_sq[wid][lane] = sq;
    __syncthreads();
    if (threadIdx.x < 32) {
        float ts = 0.f, tq = 0.f;
#pragma unroll
        for (int w = 0; w < 8; w++) { ts += s_sum[w][threadIdx.x]; tq += s_sq[w][threadIdx.x]; }
        atomicAdd(&g_colsum[threadIdx.x], ts);
        atomicAdd(&g_colsq[threadIdx.x], tq);
    }
}

__global__ void k_statsfin(const float* __restrict__ ms, float inv_n) {
    int c = threadIdx.x;
    if (c < H) {
        float mean = g_colsum[c] * inv_n;
        float m2 = g_colsq[c] * inv_n;
        float msv = ms[c];
        float var = m2 - msv * (2.f - msv) * mean * mean;
        g_mean[c] = mean;
        g_invstd[c] = rsqrtf(var + EPSV);
        g_colsum[c] = 0.f;
        g_colsq[c] = 0.f;
    }
}

// x1 = relu(gnorm(g_agg)); h2 = x1 @ W2 -> g_h
__global__ void k_norm_gemm(const float* __restrict__ gnw, const float* __restrict__ gnb,
                            const float* __restrict__ ms, const float* __restrict__ w2, int n) {
    __shared__ float ws[H * H];
    for (int i = threadIdx.x; i < H * H; i += blockDim.x) ws[i] = w2[i];
    __syncthreads();
    int lane = threadIdx.x & 31;
    int row = (blockIdx.x * blockDim.x + threadIdx.x) >> 5;
    if (row >= n) return;
    float y = g_agg[row * H + lane];
    float xv = gnw[lane] * (y - ms[lane] * g_mean[lane]) * g_invstd[lane] + gnb[lane];
    xv = fmaxf(xv, 0.f);
    float acc = 0.f;
#pragma unroll
    for (int k = 0; k < H; k++)
        acc = fmaf(__shfl_sync(FULLMASK, xv, k), ws[k * H + lane], acc);
    g_h[row * H + lane] = acc;
}

// x = relu(gnorm(g_agg2)) -> g_x
__global__ void k_norm_only(const float* __restrict__ gnw, const float* __restrict__ gnb,
                            const float* __restrict__ ms, int n) {
    int lane = threadIdx.x & 31;
    int row = (blockIdx.x * blockDim.x + threadIdx.x) >> 5;
    if (row >= n) return;
    float y = g_agg2[row * H + lane];
    float xv = gnw[lane] * (y - ms[lane] * g_mean[lane]) * g_invstd[lane] + gnb[lane];
    g_x[row * H + lane] = fmaxf(xv, 0.f);
}

// ---------------- misc setup -----------------------------------------------------
__global__ void k_wprep(const float* __restrict__ w1, const float* __restrict__ w2) {
    int idx = blockIdx.x * blockDim.x + threadIdx.x;
    if (idx >= 2048) return;
    int c = idx & 3;
    int j = (idx >> 2) & 31;
    int k4 = idx >> 7;
    g_w1t[idx] = w1[(k4 * 4 + c) * 32 + j];
    g_w2t[idx] = w2[(k4 * 4 + c) * 32 + j];
}

// per-node triple range start: first t with src[tri_a[t]] >= i
__global__ void k_bounds(const int* __restrict__ src, const int* __restrict__ tri_a,
                         int n, int T) {
    int i = blockIdx.x * blockDim.x + threadIdx.x;
    if (i > n) return;
    int lo = 0, hi = T;
    while (lo < hi) {
        int mid = (lo + hi) >> 1;
        int node = src[tri_a[mid]];
        if (node < i) lo = mid + 1; else hi = mid;
    }
    g_tlo[i] = lo;
}

__global__ void k_maxseg(const int* __restrict__ tri_seg, int n) {
    int lane = threadIdx.x & 31;
    int i = (blockIdx.x * blockDim.x + threadIdx.x) >> 5;
    if (i >= n) return;
    int t0 = g_tlo[i], t1 = g_tlo[i + 1];
    int mx = -1;
    for (int t = t0 + lane; t < t1; t += 32) mx = max(mx, tri_seg[t]);
#pragma unroll
    for (int off = 16; off; off >>= 1) mx = max(mx, __shfl_xor_sync(FULLMASK, mx, off));
    if (lane == 0) g_mx[i] = mx;
}

// zlo[i] = 1 + max(mx[0..i-1]); zlo[n] = tail start.
__global__ void __launch_bounds__(1024) k_prefix(int n) {
    __shared__ int part[1024];
    int tid = threadIdx.x;
    int chunk = (n + 1 + 1023) / 1024;
    int lo = tid * chunk;
    int hi = min(lo + chunk, n + 1);
    int pm = -1;
    for (int i = lo; i < hi; i++)
        if (i < n) pm = max(pm, g_mx[i]);
    part[tid] = pm;
    __syncthreads();
    __shared__ int excl[1024];
    int run = -1;
    if (tid == 0) {
        for (int t = 0; t < 1024; t++) { excl[t] = run; run = max(run, part[t]); }
    }
    __syncthreads();
    run = excl[tid];
    for (int i = lo; i < hi; i++) {
        g_zlo[i] = run + 1;
        if (i < n) run = max(run, g_mx[i]);
    }
}

// ---------------- edge MLPs -----------------------------------------------------
__global__ void k_edge_mlp(const int* __restrict__ src, const int* __restrict__ dst,
                           const float* __restrict__ b1, const float* __restrict__ b2, int m) {
    __shared__ float4 sw1[512];
    __shared__ float4 sw2[512];
    {
        const float4* w1f4 = reinterpret_cast<const float4*>(g_w1t);
        const float4* w2f4 = reinterpret_cast<const float4*>(g_w2t);
        for (int i = threadIdx.x; i < 512; i += blockDim.x) { sw1[i] = w1f4[i]; sw2[i] = w2f4[i]; }
    }
    __syncthreads();
    int lane = threadIdx.x & 31;
    int e = (blockIdx.x * blockDim.x + threadIdx.x) >> 5;
    if (e >= m) return;
    int s = src[e], d = dst[e];
    float xs = g_x[s * H + lane];
    float xd = g_x[d * H + lane];
    float a1 = b1[lane], a2 = b2[lane];
#pragma unroll
    for (int k4 = 0; k4 < 8; k4++) {
        float4 w1v = sw1[k4 * 32 + lane];
        float4 w2v = sw2[k4 * 32 + lane];
        float v0 = __shfl_sync(FULLMASK, xs, k4 * 4 + 0);
        float v1 = __shfl_sync(FULLMASK, xs, k4 * 4 + 1);
        float v2 = __shfl_sync(FULLMASK, xs, k4 * 4 + 2);
        float v3 = __shfl_sync(FULLMASK, xs, k4 * 4 + 3);
        a1 = fmaf(v0, w1v.x, a1); a2 = fmaf(v0, w2v.x, a2);
        a1 = fmaf(v1, w1v.y, a1); a2 = fmaf(v1, w2v.y, a2);
        a1 = fmaf(v2, w1v.z, a1); a2 = fmaf(v2, w2v.z, a2);
        a1 = fmaf(v3, w1v.w, a1); a2 = fmaf(v3, w2v.w, a2);
    }
#pragma unroll
    for (int k4 = 8; k4 < 16; k4++) {
        float4 w1v = sw1[k4 * 32 + lane];
        float4 w2v = sw2[k4 * 32 + lane];
        float v0 = __shfl_sync(FULLMASK, xd, (k4 - 8) * 4 + 0);
        float v1 = __shfl_sync(FULLMASK, xd, (k4 - 8) * 4 + 1);
        float v2 = __shfl_sync(FULLMASK, xd, (k4 - 8) * 4 + 2);
        float v3 = __shfl_sync(FULLMASK, xd, (k4 - 8) * 4 + 3);
        a1 = fmaf(v0, w1v.x, a1); a2 = fmaf(v0, w2v.x, a2);
        a1 = fmaf(v1, w1v.y, a1); a2 = fmaf(v1, w2v.y, a2);
        a1 = fmaf(v2, w1v.z, a1); a2 = fmaf(v2, w2v.z, a2);
        a1 = fmaf(v3, w1v.w, a1); a2 = fmaf(v3, w2v.w, a2);
    }
    g_xe[e * H + lane] = fmaxf(a1, 0.f);
    g_mul[e * H + lane] = fmaxf(a2, 0.f);
}

// ---------------- fused zero+scatter (race-free disjoint ranges) ---------------
__global__ void __launch_bounds__(256) k_scatter_fused(
        const int* __restrict__ tri_a, const int* __restrict__ tri_b,
        const int* __restrict__ tri_seg, int n, int n_out) {
    int i = blockIdx.x;
    int tid = threadIdx.x;
    if (i == n) {
        int rlo = g_zlo[n];
        float4 z = make_float4(0.f, 0.f, 0.f, 0.f);
        float4* base = reinterpret_cast<float4*>(g_bmm) + (size_t)rlo * 8;
        long long nz = (long long)(n_out - rlo) * 8;
        for (long long k = tid; k < nz; k += blockDim.x) base[k] = z;
        return;
    }
    int t0 = g_tlo[i], t1 = g_tlo[i + 1];
    if (t0 == t1) return;
    int rlo = g_zlo[i];
    int rhi = g_mx[i];
    float4 z = make_float4(0.f, 0.f, 0.f, 0.f);
    float4* base = reinterpret_cast<float4*>(g_bmm) + (size_t)rlo * 8;
    long long nz = (long long)(rhi + 1 - rlo) * 8;
    for (long long k = tid; k < nz; k += blockDim.x) base[k] = z;
    __syncthreads();
    long long nt = (long long)(t1 - t0) * 8;
    for (long long k = tid; k < nt; k += blockDim.x) {
        int t = t0 + (int)(k >> 3);
        int sub = (int)(k & 7);
        int a = tri_a[t], b = tri_b[t], sg = tri_seg[t];
        const float4 xe4 = *reinterpret_cast<const float4*>(&g_xe[a * H + sub * 4]);
        const float4 mu4 = *reinterpret_cast<const float4*>(&g_mul[b * H + sub * 4]);
        float4 p = make_float4(xe4.x * mu4.x, xe4.y * mu4.y, xe4.z * mu4.z, xe4.w * mu4.w);
        red_add_f4(&g_bmm[(size_t)sg * H + sub * 4], p);
    }
}

// ---------------- Gram accumulation via tensor cores (3xTF32 mma) ----------------
// G(32x32) = sum_rows v v^T. Warp processes 8 rows per step. Lane (g=lane>>2,
// t=lane&3) loads e[p][q] = row_{t+4p}[g+8q]; these directly form mma fragments.
// 3xTF32: G += hi*hi + hi*lo + lo*hi  (fp32-grade accuracy).
__global__ void __launch_bounds__(256) k_gram(const float* __restrict__ is_edge, int n) {
    int lane = threadIdx.x & 31;
    int wid = threadIdx.x >> 5;
    int gwarp = (blockIdx.x * blockDim.x + threadIdx.x) >> 5;
    int nwarps = (gridDim.x * blockDim.x) >> 5;
    int gq = lane >> 2;   // 0..7 (groupID)
    int tq = lane & 3;    // 0..3 (threadID in group)

    float C[2][4][4];
#pragma unroll
    for (int ti = 0; ti < 2; ti++)
#pragma unroll
        for (int bj = 0; bj < 4; bj++)
#pragma unroll
            for (int k = 0; k < 4; k++) C[ti][bj][k] = 0.f;
    float sp[4] = {0.f, 0.f, 0.f, 0.f};
    float wp[4] = {0.f, 0.f, 0.f, 0.f};

    int nchunks = (n + 7) >> 3;
    for (int c = gwarp; c < nchunks; c += nwarps) {
        int ra = (c << 3) + tq;
        int rb = ra + 4;
        bool va = ra < n, vb = rb < n;
        float ie0 = va ? __ldg(&is_edge[ra]) : 0.f;
        float ie1 = vb ? __ldg(&is_edge[rb]) : 0.f;
        float e0[4], e1[4];
#pragma unroll
        for (int q = 0; q < 4; q++) {
            e0[q] = va ? g_bmm[(size_t)ra * H + gq + 8 * q] : 0.f;
            e1[q] = vb ? g_bmm[(size_t)rb * H + gq + 8 * q] : 0.f;
        }
#pragma unroll
        for (int q = 0; q < 4; q++) {
            sp[q] += e0[q] + e1[q];
            wp[q] = fmaf(ie0, e0[q], fmaf(ie1, e1[q], wp[q]));
        }
        unsigned hi0[4], hi1[4], lo0[4], lo1[4];
#pragma unroll
        for (int q = 0; q < 4; q++) {
            unsigned hv = cvt_tf32(e0[q]);
            hi0[q] = hv;
            lo0[q] = cvt_tf32(e0[q] - __uint_as_float(hv));
            hv = cvt_tf32(e1[q]);
            hi1[q] = hv;
            lo1[q] = cvt_tf32(e1[q] - __uint_as_float(hv));
        }
#pragma unroll
        for (int ti = 0; ti < 2; ti++) {
#pragma unroll
            for (int bj = 0; bj < 4; bj++) {
                MMA_TF32(C[ti][bj], hi0[2 * ti], hi0[2 * ti + 1], hi1[2 * ti], hi1[2 * ti + 1],
                         hi0[bj], hi1[bj]);
                MMA_TF32(C[ti][bj], hi0[2 * ti], hi0[2 * ti + 1], hi1[2 * ti], hi1[2 * ti + 1],
                         lo0[bj], lo1[bj]);
                MMA_TF32(C[ti][bj], lo0[2 * ti], lo0[2 * ti + 1], lo1[2 * ti], lo1[2 * ti + 1],
                         hi0[bj], hi1[bj]);
            }
        }
    }

    // reduce column sums over the 4 t-lanes of each g-group (result in t==0 lane)
#pragma unroll
    for (int q = 0; q < 4; q++) {
        sp[q] += __shfl_down_sync(FULLMASK, sp[q], 2);
        sp[q] += __shfl_down_sync(FULLMASK, sp[q], 1);
        wp[q] += __shfl_down_sync(FULLMASK, wp[q], 2);
        wp[q] += __shfl_down_sync(FULLMASK, wp[q], 1);
    }

    __shared__ float red[8][H * H];
    __shared__ float ss[8][H];
    __shared__ float ww[8][H];
#pragma unroll
    for (int ti = 0; ti < 2; ti++)
#pragma unroll
        for (int bj = 0; bj < 4; bj++) {
            int r0 = ti * 16 + gq;
            int c0 = bj * 8 + 2 * tq;
            red[wid][r0 * H + c0]           = C[ti][bj][0];
            red[wid][r0 * H + c0 + 1]       = C[ti][bj][1];
            red[wid][(r0 + 8) * H + c0]     = C[ti][bj][2];
            red[wid][(r0 + 8) * H + c0 + 1] = C[ti][bj][3];
        }
    if (tq == 0) {
#pragma unroll
        for (int q = 0; q < 4; q++) { ss[wid][gq + 8 * q] = sp[q]; ww[wid][gq + 8 * q] = wp[q]; }
    }
    __syncthreads();
    for (int e = threadIdx.x; e < H * H; e += blockDim.x) {
        float tsum = 0.f;
#pragma unroll
        for (int w8 = 0; w8 < 8; w8++) tsum += red[w8][e];
        atomicAdd(&g_gram[e], tsum);
    }
    if (threadIdx.x < 32) {
        float ts = 0.f, tw = 0.f;
#pragma unroll
        for (int w8 = 0; w8 < 8; w8++) { ts += ss[w8][threadIdx.x]; tw += ww[w8][threadIdx.x]; }
        atomicAdd(&g_gs[threadIdx.x], ts);
        atomicAdd(&g_gw[threadIdx.x], tw);
    }
}

__global__ void k_gramfin(const float* __restrict__ w3, const float* __restrict__ b3,
                          const float* __restrict__ ms, float fn, float fm) {
    int j = threadIdx.x;
    if (j >= H) return;
    float Wc[34];
#pragma unroll 1
    for (int k = 0; k < 33; k++) Wc[k] = w3[k * H + j];
    Wc[33] = b3[j];
    float inv_n = 1.f / fn;
    double q = 0.0;
    for (int k = 0; k < 34; k++) {
        double rowdot = 0.0;
        for (int l = 0; l < 34; l++) {
            float gkl;
            if (k < 32) {
                if (l < 32) gkl = g_gram[k * H + l];
                else if (l == 32) gkl = g_gw[k];
                else gkl = g_gs[k];
            } else if (k == 32) {
                if (l < 32) gkl = g_gw[l];
                else gkl = fm;
            } else {
                if (l < 32) gkl = g_gs[l];
                else if (l == 32) gkl = fm;
                else gkl = fn;
            }
            rowdot += (double)gkl * (double)Wc[l];
        }
        q += (double)Wc[k] * rowdot;
    }
    double msum = 0.0;
    for (int k = 0; k < 32; k++) msum += (double)g_gs[k] * (double)Wc[k];
    msum += (double)fm * (double)Wc[32];
    msum += (double)fn * (double)Wc[33];
    float mean = (float)(msum * (double)inv_n);
    float m2 = (float)(q * (double)inv_n);
    float msv = ms[j];
    float var = m2 - msv * (2.f - msv) * mean * mean;
    g_mean[j] = mean;
    g_invstd[j] = rsqrtf(var + EPSV);
}

// ---------------- final query kernel --------------------------------------------
__device__ __forceinline__ float compute_xo(int row, int lane, const float* ws,
                                            const float* __restrict__ is_edge,
                                            const float* __restrict__ b3,
                                            const float* __restrict__ gn3w,
                                            const float* __restrict__ gn3b,
                                            const float* __restrict__ gn3ms) {
    float v = g_bmm[(size_t)row * H + lane];
    float acc = fmaf(is_edge[row], ws[32 * H + lane], b3[lane]);
#pragma unroll
    for (int k = 0; k < H; k++)
        acc = fmaf(__shfl_sync(FULLMASK, v, k), ws[k * H + lane], acc);
    float xo = gn3w[lane] * (acc - gn3ms[lane] * g_mean[lane]) * g_invstd[lane] + gn3b[lane];
    return fmaxf(xo, 0.f);
}

__global__ void k_final(const int* __restrict__ pred_idx, const int* __restrict__ trans_perm,
                        const float* __restrict__ pred_mask, const int* __restrict__ pos,
                        const float* __restrict__ is_edge,
                        const float* __restrict__ w3, const float* __restrict__ b3,
                        const float* __restrict__ gn3w, const float* __restrict__ gn3b,
                        const float* __restrict__ gn3ms,
                        const float* __restrict__ lw, const float* __restrict__ lb,
                        float* __restrict__ out, int P) {
    __shared__ float ws[33 * H];
    for (int i = threadIdx.x; i < 33 * H; i += blockDim.x) ws[i] = w3[i];
    __syncthreads();
    int lane = threadIdx.x & 31;
    int p = (blockIdx.x * blockDim.x + threadIdx.x) >> 5;
    if (p >= P) return;
    int r = pred_idx[p];
    int rt = trans_perm[r];
    float mask = pred_mask[p];
    float xo_r = compute_xo(r, lane, ws, is_edge, b3, gn3w, gn3b, gn3ms);
    float xo_t = compute_xo(rt, lane, ws, is_edge, b3, gn3w, gn3b, gn3ms);
    int i0 = pos[2 * p], j0 = pos[2 * p + 1];
    float xx = g_x[i0 * H + lane] * g_x[j0 * H + lane];
    float part = xo_r * xo_t * mask * lw[lane] + xx * lw[H + lane];
#pragma unroll
    for (int off = 16; off; off >>= 1) part += __shfl_down_sync(FULLMASK, part, off);
    if (lane == 0) out[p] = part + lb[0];
}

// ---------------- launch ---------------------------------------------------------
extern "C" void kernel_launch(void* const* d_in, const int* in_sizes, int n_in,
                              void* d_out, int out_size) {
    const float* emb     = (const float*)d_in[0];
    const float* gcn1_w  = (const float*)d_in[1];
    const float* gcn1_b  = (const float*)d_in[2];
    const float* gn1_w   = (const float*)d_in[3];
    const float* gn1_b   = (const float*)d_in[4];
    const float* gn1_ms  = (const float*)d_in[5];
    const float* gcn2_w  = (const float*)d_in[6];
    const float* gcn2_b  = (const float*)d_in[7];
    const float* gn2_w   = (const float*)d_in[8];
    const float* gn2_b   = (const float*)d_in[9];
    const float* gn2_ms  = (const float*)d_in[10];
    const float* mlp1_w  = (const float*)d_in[11];
    const float* mlp1_b  = (const float*)d_in[12];
    const float* mlp2_w  = (const float*)d_in[13];
    const float* mlp2_b  = (const float*)d_in[14];
    const float* mlp3_w  = (const float*)d_in[15];
    const float* mlp3_b  = (const float*)d_in[16];
    const float* gn3_w   = (const float*)d_in[17];
    const float* gn3_b   = (const float*)d_in[18];
    const float* gn3_ms  = (const float*)d_in[19];
    const float* lind_w  = (const float*)d_in[20];
    const float* lind_b  = (const float*)d_in[21];
    const float* is_edge = (const float*)d_in[22];
    const float* pred_mask = (const float*)d_in[23];
    const int* x_nodes   = (const int*)d_in[24];
    const int* ei        = (const int*)d_in[25];
    const int* pos       = (const int*)d_in[26];
    const int* tri_a     = (const int*)d_in[27];
    const int* tri_b     = (const int*)d_in[28];
    const int* tri_seg   = (const int*)d_in[29];
    const int* trans_perm= (const int*)d_in[30];
    const int* pred_idx  = (const int*)d_in[31];

    int N     = in_sizes[24];
    int m     = in_sizes[25] / 2;
    int n_out = in_sizes[22];
    int T     = in_sizes[27];
    int P     = in_sizes[23];

    const int* src = ei;
    const int* dst = ei + m;

    int nodeWarpBlocks = (N * H + 255) / 256;
    int edgeWarpBlocks = (int)(((long long)m * H + 255) / 256);
    int queryWarpBlocks = (P * H + 255) / 256;

    // slots 1-4 (slot 4 profiled = fused gather+post layer 1)
    k_prep<<<(N + 256) / 256, 256>>>(src, N, m);                          // 1
    k_deg<<<(m + 255) / 256, 256>>>(dst, m);                              // 2
    k_embed_gemm<<<nodeWarpBlocks, 256>>>(emb, x_nodes, gcn1_w, N);       // 3
    k_gather_post<<<nodeWarpBlocks, 256>>>(dst, gcn1_b, N, 0);            // 4 <- profiled

    k_wprep<<<8, 256>>>(mlp1_w, mlp2_w);
    k_bounds<<<(N + 256) / 256, 256>>>(src, tri_a, N, T);
    k_maxseg<<<(N * 32 + 255) / 256, 256>>>(tri_seg, N);
    k_prefix<<<1, 1024>>>(N);

    // GCN layer 1 norm + gemm
    k_statsfin<<<1, 32>>>(gn1_ms, 1.f / (float)N);
    k_norm_gemm<<<nodeWarpBlocks, 256>>>(gn1_w, gn1_b, gn1_ms, gcn2_w, N);

    // GCN layer 2
    k_gather_post<<<nodeWarpBlocks, 256>>>(dst, gcn2_b, N, 1);
    k_statsfin<<<1, 32>>>(gn2_ms, 1.f / (float)N);
    k_norm_only<<<nodeWarpBlocks, 256>>>(gn2_w, gn2_b, gn2_ms, N);

    // edge MLPs
    k_edge_mlp<<<edgeWarpBlocks, 256>>>(src, dst, mlp1_b, mlp2_b, m);

    // fused zero+scatter (race-free)
    k_scatter_fused<<<N + 1, 256>>>(tri_a, tri_b, tri_seg, N, n_out);

    // mlp3 GraphNorm statistics via tensor-core Gram (3xTF32)
    k_gram<<<444, 256>>>(is_edge, n_out);
    k_gramfin<<<1, 32>>>(mlp3_w, mlp3_b, gn3_ms, (float)n_out, (float)m);

    // final query kernel
    k_final<<<queryWarpBlocks, 256>>>(pred_idx, trans_perm, pred_mask, pos, is_edge,
                                      mlp3_w, mlp3_b, gn3_w, gn3_b, gn3_ms,
                                      lind_w, lind_b, (float*)d_out, P);
}